// round 1
// baseline (speedup 1.0000x reference)
#include <cuda_runtime.h>
#include <math.h>

#define BB 16
#define TT0 2048
#define DM 64
#define DI 128
#define DS 16

// ---------------- scratch (device globals; no allocation) ----------------
__device__ float g_h[BB*DM*TT0];       // conv_in out (b,c,t) -- also "hold"
__device__ float g_ht[BB*TT0*DM];      // transposed (b,t,c)
__device__ float g_x[(size_t)BB*TT0*DI];   // xm pre-conv (b,t,d)
__device__ float g_z[(size_t)BB*TT0*DI];
__device__ float g_xm[(size_t)BB*TT0*DI];  // post dwconv+silu
__device__ float g_delta[(size_t)BB*TT0*DI];
__device__ float g_Bmat[(size_t)BB*TT0*DS];
__device__ float g_Cmat[(size_t)BB*TT0*DS];
__device__ float g_y[(size_t)BB*TT0*DI];
__device__ float g_h2[BB*DM*TT0];      // mamba out (b,c,t)
__device__ float g_m[BB*DM*TT0];       // merge conv out / bn applied
__device__ float g_bn[2*DM];           // mean, rstd per channel
__device__ float g_u5[(size_t)BB*320*(TT0*5)];    // (b,320,10240)
__device__ float g_u10[(size_t)BB*128*(TT0*10)];  // (b,128,20480)

// ---------------- generic k=15 conv, tiled, optional pixel-shuffle -------
// OG*TG threads. Tile: (OG*RO) out channels x (TG*RT) time steps.
// R: pixel-shuffle factor on output channels. ACT: 0 none, 1 leaky.
template<int OG, int RO, int TG, int RT, int CC, int R, int ACT>
__global__ void conv15_kernel(const float* __restrict__ x,
                              const float* __restrict__ w,
                              const float* __restrict__ bias,
                              float* __restrict__ out,
                              int Cin, int Cout, int T) {
    constexpr int TILE_T = TG * RT;
    constexpr int TTP = TILE_T + 14;          // valid columns
    constexpr int ROWLEN = TILE_T + 16;       // padded row
    constexpr int NV = (RT + 14 + 3) / 4;     // float4 window loads
    __shared__ float s_in[CC][ROWLEN];

    const int b  = blockIdx.z;
    const int o0 = blockIdx.y * (OG * RO);
    const int t0 = blockIdx.x * TILE_T;
    const int tid = threadIdx.x;
    const int og = tid / TG;
    const int tg = tid % TG;
    const int o_base = o0 + og * RO;
    const int t_base = t0 + tg * RT;

    float acc[RO][RT];
#pragma unroll
    for (int i = 0; i < RO; i++)
#pragma unroll
        for (int j = 0; j < RT; j++) acc[i][j] = 0.f;

    const float* xb = x + (size_t)b * Cin * T;

    for (int c0 = 0; c0 < Cin; c0 += CC) {
        __syncthreads();
        // stage input chunk [c0, c0+CC) x [t0-7, t0+TILE_T+7)
        for (int idx = tid; idx < CC * TTP; idx += OG * TG) {
            int ci  = idx / TTP;
            int col = idx % TTP;
            int c = c0 + ci;
            int t = t0 + col - 7;
            float v = 0.f;
            if (c < Cin && t >= 0 && t < T) v = xb[(size_t)c * T + t];
            s_in[ci][col] = v;
        }
        __syncthreads();
        const int cmax = (Cin - c0 < CC) ? (Cin - c0) : CC;
        for (int ci = 0; ci < cmax; ci++) {
            // load sliding window into registers (vectorized)
            float xw[NV * 4];
            const float4* rp = reinterpret_cast<const float4*>(&s_in[ci][tg * RT]);
#pragma unroll
            for (int q = 0; q < NV; q++) {
                float4 v = rp[q];
                xw[4*q+0] = v.x; xw[4*q+1] = v.y; xw[4*q+2] = v.z; xw[4*q+3] = v.w;
            }
            const int cc = c0 + ci;
#pragma unroll
            for (int i = 0; i < RO; i++) {
                const float* wp = w + ((size_t)(o_base + i) * Cin + cc) * 15;
#pragma unroll
                for (int k = 0; k < 15; k++) {
                    float wv = __ldg(wp + k);
#pragma unroll
                    for (int j = 0; j < RT; j++)
                        acc[i][j] = fmaf(wv, xw[j + k], acc[i][j]);
                }
            }
        }
    }

    const int CoutR = Cout / R;
    const size_t TR = (size_t)T * R;
#pragma unroll
    for (int i = 0; i < RO; i++) {
        int oc = o_base + i;
        float bv = __ldg(bias + oc);
        int c = oc / R;
        int r = oc % R;
        float* op = out + ((size_t)b * CoutR + c) * TR + r;
#pragma unroll
        for (int j = 0; j < RT; j++) {
            float v = acc[i][j] + bv;
            if (ACT == 1) v = (v >= 0.f) ? v : 0.01f * v;
            op[(size_t)(t_base + j) * R] = v;
        }
    }
}

// ---------------- transpose (b,c,t) -> (b,t,c) ---------------------------
__global__ void transpose_kernel() {
    __shared__ float tile[32][33];
    int b = blockIdx.z;
    int c0 = blockIdx.y * 32;
    int t0 = blockIdx.x * 32;
    int tx = threadIdx.x, ty = threadIdx.y;
#pragma unroll
    for (int i = 0; i < 32; i += 8)
        tile[ty + i][tx] = g_h[((size_t)(b * DM + c0 + ty + i)) * TT0 + t0 + tx];
    __syncthreads();
#pragma unroll
    for (int i = 0; i < 32; i += 8)
        g_ht[((size_t)b * TT0 + t0 + ty + i) * DM + c0 + tx] = tile[tx][ty + i];
}

// ---------------- rmsnorm + in_proj --------------------------------------
__global__ void rmsnorm_inproj_kernel(const float* __restrict__ norm_w,
                                      const float* __restrict__ Wp) {
    int t = blockIdx.x, b = blockIdx.y;
    int tid = threadIdx.x; // 256
    __shared__ float s_xn[DM];
    __shared__ float s_red[8];
    const size_t bt = (size_t)b * TT0 + t;
    const float* xp = g_ht + bt * DM;
    float v = (tid < DM) ? xp[tid] : 0.f;
    float sq = v * v;
#pragma unroll
    for (int o = 16; o; o >>= 1) sq += __shfl_down_sync(0xffffffffu, sq, o);
    if ((tid & 31) == 0) s_red[tid >> 5] = sq;
    __syncthreads();
    float ms = (s_red[0] + s_red[1]) * (1.f / DM);
    float rstd = rsqrtf(ms + 1e-5f);
    if (tid < DM) s_xn[tid] = v * rstd * norm_w[tid];
    __syncthreads();
    float acc = 0.f;
    const float* wr = Wp + tid * DM;
#pragma unroll
    for (int c = 0; c < DM; c++) acc = fmaf(s_xn[c], __ldg(wr + c), acc);
    if (tid < DI) g_x[bt * DI + tid] = acc;
    else          g_z[bt * DI + (tid - DI)] = acc;
}

// ---------------- depthwise causal conv (k=4) + silu ---------------------
__global__ void dwconv_silu_kernel(const float* __restrict__ w,
                                   const float* __restrict__ bias) {
    size_t i = (size_t)blockIdx.x * blockDim.x + threadIdx.x;
    if (i >= (size_t)BB * TT0 * DI) return;
    int d = (int)(i % DI);
    size_t bt = i / DI;
    int t = (int)(bt % TT0);
    float acc = bias[d];
#pragma unroll
    for (int k = 0; k < 4; k++) {
        int tt = t - 3 + k;
        if (tt >= 0) acc = fmaf(w[d * 4 + k], g_x[(bt - t + tt) * DI + d], acc);
    }
    acc = acc / (1.f + __expf(-acc));
    g_xm[i] = acc;
}

// ---------------- x_proj + dt_proj + softplus ----------------------------
__global__ void xproj_dt_kernel(const float* __restrict__ Wx,
                                const float* __restrict__ Wd,
                                const float* __restrict__ bd) {
    int t = blockIdx.x, b = blockIdx.y;
    int tid = threadIdx.x; // 128
    __shared__ float s_xm[DI];
    __shared__ float s_db[36];
    const size_t bt = (size_t)b * TT0 + t;
    s_xm[tid] = g_xm[bt * DI + tid];
    __syncthreads();
    if (tid < 36) {
        float acc = 0.f;
        const float* wr = Wx + tid * DI;
#pragma unroll
        for (int d = 0; d < DI; d++) acc = fmaf(s_xm[d], __ldg(wr + d), acc);
        s_db[tid] = acc;
    }
    __syncthreads();
    {
        float acc = bd[tid];
#pragma unroll
        for (int r = 0; r < 4; r++) acc = fmaf(s_db[r], Wd[tid * 4 + r], acc);
        g_delta[bt * DI + tid] = (acc > 15.f) ? acc : log1pf(__expf(acc));
    }
    if (tid < DS)            g_Bmat[bt * DS + tid] = s_db[4 + tid];
    else if (tid < 2 * DS)   g_Cmat[bt * DS + tid - DS] = s_db[20 + tid - DS];
}

// ---------------- selective scan -----------------------------------------
__global__ void scan_kernel(const float* __restrict__ A_log,
                            const float* __restrict__ Dp) {
    int b = blockIdx.x;
    int d = threadIdx.x; // 128
    __shared__ float sB[DS], sC[DS];
    float A[DS];
#pragma unroll
    for (int n = 0; n < DS; n++) A[n] = -__expf(A_log[d * DS + n]);
    float h[DS];
#pragma unroll
    for (int n = 0; n < DS; n++) h[n] = 0.f;
    float Dv = Dp[d];
    for (int t = 0; t < TT0; t++) {
        size_t bt = (size_t)b * TT0 + t;
        if (d < DS)            sB[d] = g_Bmat[bt * DS + d];
        else if (d < 2 * DS)   sC[d - DS] = g_Cmat[bt * DS + d - DS];
        __syncthreads();
        float dt = g_delta[bt * DI + d];
        float u  = g_xm[bt * DI + d];
        float du = dt * u;
        float y = 0.f;
#pragma unroll
        for (int n = 0; n < DS; n++) {
            float dA = __expf(dt * A[n]);
            h[n] = fmaf(h[n], dA, du * sB[n]);
            y = fmaf(h[n], sC[n], y);
        }
        g_y[bt * DI + d] = fmaf(u, Dv, y);
        __syncthreads();
    }
}

// ---------------- gate * silu(z), out_proj, residual, transpose back -----
__global__ void gate_outproj_kernel(const float* __restrict__ Wo) {
    int t = blockIdx.x, b = blockIdx.y;
    int tid = threadIdx.x; // 128
    __shared__ float s_g[DI];
    const size_t bt = (size_t)b * TT0 + t;
    float z = g_z[bt * DI + tid];
    s_g[tid] = g_y[bt * DI + tid] * (z / (1.f + __expf(-z)));
    __syncthreads();
    if (tid < DM) {
        float acc = 0.f;
        const float* wr = Wo + tid * DI;
#pragma unroll
        for (int d = 0; d < DI; d++) acc = fmaf(s_g[d], __ldg(wr + d), acc);
        g_h2[((size_t)(b * DM + tid)) * TT0 + t] = g_ht[bt * DM + tid] + acc;
    }
}

// ---------------- batchnorm stats ----------------------------------------
__global__ void bn_stats_kernel() {
    int c = blockIdx.x;
    float s = 0.f, q = 0.f;
    for (int i = threadIdx.x; i < BB * TT0; i += 256) {
        int b = i >> 11;
        int t = i & 2047;
        float v = g_m[((size_t)(b * DM + c)) * TT0 + t];
        s += v; q += v * v;
    }
#pragma unroll
    for (int o = 16; o; o >>= 1) {
        s += __shfl_down_sync(0xffffffffu, s, o);
        q += __shfl_down_sync(0xffffffffu, q, o);
    }
    __shared__ float rs[8], rq[8];
    if ((threadIdx.x & 31) == 0) { rs[threadIdx.x >> 5] = s; rq[threadIdx.x >> 5] = q; }
    __syncthreads();
    if (threadIdx.x == 0) {
        float S = 0.f, Q = 0.f;
#pragma unroll
        for (int i = 0; i < 8; i++) { S += rs[i]; Q += rq[i]; }
        const float inv = 1.f / (BB * TT0);
        float mean = S * inv;
        float var = Q * inv - mean * mean;
        g_bn[c] = mean;
        g_bn[DM + c] = rsqrtf(var + 1e-5f);
    }
}

// ---------------- batchnorm apply + residual (hold) ----------------------
__global__ void bn_apply_kernel(const float* __restrict__ gamma,
                                const float* __restrict__ beta) {
    size_t i = (size_t)blockIdx.x * blockDim.x + threadIdx.x;
    if (i >= (size_t)BB * DM * TT0) return;
    int c = (int)((i / TT0) % DM);
    float v = (g_m[i] - g_bn[c]) * g_bn[DM + c] * gamma[c] + beta[c] + g_h[i];
    g_m[i] = v;
}

// ---------------- host launcher ------------------------------------------
extern "C" void kernel_launch(void* const* d_in, const int* in_sizes, int n_in,
                              void* d_out, int out_size) {
    (void)in_sizes; (void)n_in; (void)out_size;
    const float* x          = (const float*)d_in[0];
    const float* conv_in_w  = (const float*)d_in[1];
    const float* conv_in_b  = (const float*)d_in[2];
    const float* norm_w     = (const float*)d_in[3];
    const float* in_proj_w  = (const float*)d_in[4];
    const float* dwconv_w   = (const float*)d_in[5];
    const float* dwconv_b   = (const float*)d_in[6];
    const float* x_proj_w   = (const float*)d_in[7];
    const float* dt_proj_w  = (const float*)d_in[8];
    const float* dt_proj_b  = (const float*)d_in[9];
    const float* A_log      = (const float*)d_in[10];
    const float* Dvec       = (const float*)d_in[11];
    const float* out_proj_w = (const float*)d_in[12];
    const float* merge_w    = (const float*)d_in[13];
    const float* merge_b    = (const float*)d_in[14];
    const float* bn_g       = (const float*)d_in[15];
    const float* bn_b       = (const float*)d_in[16];
    const float* up1_w      = (const float*)d_in[17];
    const float* up1_b      = (const float*)d_in[18];
    const float* up2_w      = (const float*)d_in[19];
    const float* up2_b      = (const float*)d_in[20];
    const float* out_w      = (const float*)d_in[21];
    const float* out_b      = (const float*)d_in[22];

    float *p_h, *p_h2, *p_m, *p_u5, *p_u10;
    cudaGetSymbolAddress((void**)&p_h,   g_h);
    cudaGetSymbolAddress((void**)&p_h2,  g_h2);
    cudaGetSymbolAddress((void**)&p_m,   g_m);
    cudaGetSymbolAddress((void**)&p_u5,  g_u5);
    cudaGetSymbolAddress((void**)&p_u10, g_u10);

    // 1) conv_in: (16,12,2048) -> g_h (16,64,2048), leaky
    conv15_kernel<16,4,16,8,16,1,1><<<dim3(TT0/128, 1, BB), 256>>>(
        x, conv_in_w, conv_in_b, p_h, 12, 64, TT0);

    // 2) transpose to (b,t,c)
    transpose_kernel<<<dim3(TT0/32, DM/32, BB), dim3(32, 8)>>>();

    // 3) rmsnorm + in_proj
    rmsnorm_inproj_kernel<<<dim3(TT0, BB), 256>>>(norm_w, in_proj_w);

    // 4) depthwise causal conv + silu
    {
        size_t N = (size_t)BB * TT0 * DI;
        dwconv_silu_kernel<<<(unsigned)((N + 255) / 256), 256>>>(dwconv_w, dwconv_b);
    }

    // 5) x_proj + dt_proj + softplus
    xproj_dt_kernel<<<dim3(TT0, BB), 128>>>(x_proj_w, dt_proj_w, dt_proj_b);

    // 6) selective scan
    scan_kernel<<<BB, DI>>>(A_log, Dvec);

    // 7) gate + out_proj + residual -> g_h2 (b,c,t)
    gate_outproj_kernel<<<dim3(TT0, BB), 128>>>(out_proj_w);

    // 8) merge conv -> g_m
    conv15_kernel<16,4,16,8,16,1,0><<<dim3(TT0/128, 1, BB), 256>>>(
        p_h2, merge_w, merge_b, p_m, 64, 64, TT0);

    // 9) batchnorm stats
    bn_stats_kernel<<<DM, 256>>>();

    // 10) batchnorm apply + hold residual
    {
        size_t N = (size_t)BB * DM * TT0;
        bn_apply_kernel<<<(unsigned)((N + 255) / 256), 256>>>(bn_g, bn_b);
    }

    // 11) up1: conv (64->1600) + shuffle r=5 + leaky -> g_u5 (16,320,10240)
    conv15_kernel<16,4,16,8,16,5,1><<<dim3(TT0/128, 1600/64, BB), 256>>>(
        p_m, up1_w, up1_b, p_u5, 64, 1600, TT0);

    // 12) up2: conv (320->256) on T=10240 + shuffle r=2 + leaky -> g_u10
    conv15_kernel<16,4,16,8,16,2,1><<<dim3((TT0*5)/128, 256/64, BB), 256>>>(
        p_u5, up2_w, up2_b, p_u10, 320, 256, TT0 * 5);

    // 13) out conv: (128->12) on T=20480 -> d_out
    conv15_kernel<4,3,64,4,16,1,0><<<dim3((TT0*10)/256, 1, BB), 256>>>(
        p_u10, out_w, out_b, (float*)d_out, 128, 12, TT0 * 10);
}